// round 15
// baseline (speedup 1.0000x reference)
#include <cuda_runtime.h>
#include <cuda_bf16.h>
#include <cuda_fp16.h>
#include <math.h>

// Problem constants
#define PH     5
#define NCOIL  16          // ch*d = 8*2
#define NIM    320         // H = W
#define KOS    640         // 2x oversampled grid
#define KLEN   16000
#define JTAPS  6
#define ALPHA_F 14.04f     // 2.34 * 6
#define PI_F   3.14159265358979323846f

// ---------------------------------------------------------------------------
// Static device scratch (no allocations allowed)
//   g_Rh: stage-1 out fp16, layout [p][q][c][n]
//   g_Gh: stage-2 out fp16, layout [p][k][q][c]  (coil innermost for interp)
// ---------------------------------------------------------------------------
__device__ __half2 g_Rh[PH * KOS * NCOIL * NIM];     // 65.5 MB
__device__ __half2 g_Gh[PH * KOS * KOS * NCOIL];     // 131 MB
__device__ float   g_sh[NIM];                        // apodization (sh == sw)
__device__ float   g_inv_i0a;                        // 1 / I0(alpha)

// ---------------------------------------------------------------------------
// Packed f32x2 helpers: one u2 = one complex value (re, im).
// ---------------------------------------------------------------------------
typedef unsigned long long u2;

__device__ __forceinline__ u2 pk2(float lo, float hi) {
    u2 r; asm("mov.b64 %0, {%1, %2};" : "=l"(r) : "f"(lo), "f"(hi)); return r;
}
__device__ __forceinline__ void upk2(float& lo, float& hi, u2 v) {
    asm("mov.b64 {%0, %1}, %2;" : "=f"(lo), "=f"(hi) : "l"(v));
}
__device__ __forceinline__ u2 dup2(float x) { return pk2(x, x); }
__device__ __forceinline__ u2 swap2(u2 v) {
    float a, b; upk2(a, b, v); return pk2(b, a);
}
__device__ __forceinline__ u2 fma2(u2 a, u2 b, u2 c) {
    u2 d; asm("fma.rn.f32x2 %0, %1, %2, %3;" : "=l"(d) : "l"(a), "l"(b), "l"(c)); return d;
}
__device__ __forceinline__ u2 mul2(u2 a, u2 b) {
    u2 d; asm("mul.rn.f32x2 %0, %1, %2;" : "=l"(d) : "l"(a), "l"(b)); return d;
}
// acc += z * (wr + i wi), z packed (re,im); constants fold to immediates.
#define CFMA(acc, z, wr, wi)                                \
    do {                                                    \
        acc = fma2((z),        dup2(wr), acc);              \
        acc = fma2(swap2(z), pk2(-(wi), (wi)), acc);        \
    } while (0)

// complex mult: a * b where b = (bc = dup(cos), bs = (-sin, sin))
__device__ __forceinline__ u2 cmul(u2 a, u2 bc, u2 bs) {
    return fma2(swap2(a), bs, mul2(a, bc));
}

// ---------------------------------------------------------------------------
// Compile-time twiddle tables
// ---------------------------------------------------------------------------
__device__ constexpr float W5R[5] = {
    1.0f, 0.30901699437495f, -0.80901699437495f, -0.80901699437495f, 0.30901699437495f };
__device__ constexpr float W5I[5] = {
    0.0f, -0.95105651629515f, -0.58778525229247f, 0.58778525229247f, 0.95105651629515f };
__device__ constexpr float W20R[20] = {
    1.0f, 0.95105651629515f, 0.80901699437495f, 0.58778525229247f, 0.30901699437495f,
    0.0f, -0.30901699437495f, -0.58778525229247f, -0.80901699437495f, -0.95105651629515f,
    -1.0f, -0.95105651629515f, -0.80901699437495f, -0.58778525229247f, -0.30901699437495f,
    0.0f, 0.30901699437495f, 0.58778525229247f, 0.80901699437495f, 0.95105651629515f };
__device__ constexpr float W20I[20] = {
    0.0f, -0.30901699437495f, -0.58778525229247f, -0.80901699437495f, -0.95105651629515f,
    -1.0f, -0.95105651629515f, -0.80901699437495f, -0.58778525229247f, -0.30901699437495f,
    0.0f, 0.30901699437495f, 0.58778525229247f, 0.80901699437495f, 0.95105651629515f,
    1.0f, 0.95105651629515f, 0.80901699437495f, 0.58778525229247f, 0.30901699437495f };

// ---------------------------------------------------------------------------
// Modified Bessel I0 (Abramowitz & Stegun, rel err ~2e-7)
// ---------------------------------------------------------------------------
__device__ __forceinline__ float i0f_dev(float x) {
    if (x < 3.75f) {
        float t = x * (1.0f / 3.75f);
        t *= t;
        return 1.0f + t * (3.5156229f + t * (3.0899424f + t * (1.2067492f +
               t * (0.2659732f + t * (0.0360768f + t * 0.0045813f)))));
    } else {
        float t = 3.75f / x;
        float p = 0.39894228f + t * (0.01328592f + t * (0.00225319f +
                  t * (-0.00157565f + t * (0.00916281f + t * (-0.02057706f +
                  t * (0.02635537f + t * (-0.01647633f + t * 0.00392377f)))))));
        return p * expf(x) * rsqrtf(x);
    }
}

// Probe: no-op kernel keeps the ncu -s/-c window landing on fft640<2>.
__global__ void probe_kernel() {}

__global__ void init_tables_kernel() {
    int n = blockIdx.x * blockDim.x + threadIdx.x;
    if (n < NIM) {
        float i0a = i0f_dev(ALPHA_F);
        if (n == 0) g_inv_i0a = 1.0f / i0a;
        float nn = (float)(n - NIM / 2);
        float u  = nn * (1.0f / (float)KOS);
        float w  = PI_F * (float)JTAPS * u;
        float z2 = w * w - ALPHA_F * ALPHA_F;
        float z  = fmaxf(sqrtf(fabsf(z2)), 1e-6f);
        float core = (z2 > 0.0f) ? (sinf(z) / z) : (sinhf(z) / z);
        float ft = core * ((float)JTAPS / i0a);
        g_sh[n] = 1.0f / ft;
    }
}

// ---------------------------------------------------------------------------
// Four-step 640-pt DFT, zero-padded length-320 input.
// Block = 128 threads = 4 warps = 4 COLUMNS (one column per warp, complex-
// packed u2). j-outer restructure keeps live registers ~96 so the kernel
// fits the 102-reg cap of (128,5) WITHOUT spills -> 20 warps/SM and free
// registers for cross-iteration ILP (the R14 profile showed regs=128
// maxed with occ=23.7%, issue=46%: latency-bound at the register wall).
//   n = 32*n1 + n2 (n1<20; nonzero n1<10),  k = k1 + 20*k2.
// MODE 1: in = fp32 image (apodized) -> g_Rh.  MODE 2: in = g_Rh -> g_Gh.
// ---------------------------------------------------------------------------
#define SQ_PAD 5                       // buf row stride (4 cols + 1 pad)
#define BUF_H2 (KOS * SQ_PAD)          // 3200 half2 = 12.8 KB

template <int MODE>
__global__ __launch_bounds__(128, 5) void fft640_kernel(
    const void* __restrict__ inv, __half2* __restrict__ out)
{
    __shared__ __half2 buf[BUF_H2];    // buf[q*SQ_PAD + col_local]

    const int tid  = threadIdx.x;
    const int w    = tid >> 5;         // warp = column 0..3
    const int lane = tid & 31;

    const int base_col = blockIdx.x * 4;
    const int col = base_col + w;

    // ---- load 10 inputs (coalesced: lane = n2), apodize in MODE 1 ----
    u2 xz[10];
    if (MODE == 1) {
        const float2* ip = (const float2*)inv + (size_t)col * NIM + lane;
        float shr = g_sh[col % NIM];
#pragma unroll
        for (int n1 = 0; n1 < 10; n1++) {
            float2 v = ip[n1 * 32];
            float s = shr * g_sh[n1 * 32 + lane];
            xz[n1] = pk2(v.x * s, v.y * s);
        }
    } else {
        const __half2* ip = (const __half2*)inv + (size_t)col * NIM + lane;
#pragma unroll
        for (int n1 = 0; n1 < 10; n1++) {
            float2 v = __half22float2(ip[n1 * 32]);
            xz[n1] = pk2(v.x, v.y);
        }
    }

    // ---- per-lane butterfly twiddles ----
    float sc_s, sc_c;
    sincospif(-(float)(lane & 15) * (1.0f / 16.0f), &sc_s, &sc_c);
    const u2 T1c = dup2((lane & 16) ? sc_c : 1.0f);
    const u2 T1s = (lane & 16) ? pk2(-sc_s, sc_s) : pk2(0.0f, 0.0f);
    sincospif(-(float)(lane & 7) * (1.0f / 8.0f), &sc_s, &sc_c);
    const u2 T2c = dup2((lane & 8) ? sc_c : 1.0f);
    const u2 T2s = (lane & 8) ? pk2(-sc_s, sc_s) : pk2(0.0f, 0.0f);
    sincospif(-(float)(lane & 3) * (1.0f / 4.0f), &sc_s, &sc_c);
    const u2 T3c = dup2((lane & 4) ? sc_c : 1.0f);
    const u2 T3s = (lane & 4) ? pk2(-sc_s, sc_s) : pk2(0.0f, 0.0f);
    const bool t4rot = (lane & 2) && (lane & 1);
    const u2 T4c = dup2(t4rot ? 0.0f : 1.0f);
    const u2 T4s = t4rot ? pk2(1.0f, -1.0f) : pk2(0.0f, 0.0f);   // *(-i)
    const u2 S16 = dup2((lane & 16) ? -1.0f : 1.0f);
    const u2 S8  = dup2((lane & 8)  ? -1.0f : 1.0f);
    const u2 S4  = dup2((lane & 4)  ? -1.0f : 1.0f);
    const u2 S2  = dup2((lane & 2)  ? -1.0f : 1.0f);
    const u2 S1  = dup2((lane & 1)  ? -1.0f : 1.0f);
    const int br = (int)(__brev((unsigned)lane) >> 27);          // bitrev5

    // ---- twiddle chains: W640^{n2 k} = wj * (W640^{5 n2})^t, k = j+5t ----
    sincospif(-(float)lane * (1.0f / 320.0f), &sc_s, &sc_c);     // W640^{n2}
    const u2 s1c = dup2(sc_c), s1s = pk2(-sc_s, sc_s);
    sincospif(-(float)lane * (1.0f / 64.0f), &sc_s, &sc_c);      // W640^{5 n2}
    const u2 s5c = dup2(sc_c), s5s = pk2(-sc_s, sc_s);
    u2 wjc = dup2(1.0f), wjs = pk2(0.0f, 0.0f);

#define BFLY2(H, TC, TS, SD)                                            \
    do {                                                                \
        float vx_, vy_;                                                 \
        upk2(vx_, vy_, v);                                              \
        float ox_ = __shfl_xor_sync(0xffffffffu, vx_, (H));             \
        float oy_ = __shfl_xor_sync(0xffffffffu, vy_, (H));             \
        u2 t_ = fma2((SD), v, pk2(ox_, oy_));                           \
        v = cmul(t_, (TC), (TS));                                       \
    } while (0)

#define CHAIN_ADV(ac_, as_, stc_, sts_)                                 \
    do {                                                                \
        float ca_, sa_, cb_, sb_, d_;                                   \
        upk2(ca_, ca_, ac_);                                            \
        upk2(d_, sa_, as_);                                             \
        upk2(cb_, cb_, stc_);                                           \
        upk2(d_, sb_, sts_);                                            \
        float nc_ = ca_ * cb_ - sa_ * sb_;                              \
        float ns_ = sa_ * cb_ + ca_ * sb_;                              \
        ac_ = dup2(nc_); as_ = pk2(-ns_, ns_);                          \
    } while (0)

    // ---- main loop: j = k % 5 ----
#pragma unroll
    for (int j = 0; j < 5; j++) {
        const int j2 = (2 * j) % 5;
        // A1: four 5-pt DFT outputs for this j (recomputed; 8 u2 live)
        u2 f0 = xz[0], f1 = xz[1], f2 = xz[2], f3 = xz[3];
        CFMA(f0, xz[4], W5R[j],  W5I[j]);
        CFMA(f0, xz[8], W5R[j2], W5I[j2]);
        CFMA(f1, xz[5], W5R[j],  W5I[j]);
        CFMA(f1, xz[9], W5R[j2], W5I[j2]);
        CFMA(f2, xz[6], W5R[j],  W5I[j]);
        CFMA(f3, xz[7], W5R[j],  W5I[j]);

        // inner twiddle chain starts at wj
        u2 tc = wjc, ts = wjs;

#pragma unroll
        for (int t = 0; t < 4; t++) {
            const int k  = j + 5 * t;
            const int ka = (2 * k) % 20, kb = (3 * k) % 20;
            u2 X = f0;
            CFMA(X, f1, W20R[k],  W20I[k]);
            CFMA(X, f2, W20R[ka], W20I[ka]);
            CFMA(X, f3, W20R[kb], W20I[kb]);

            // apply W640^{n2 k}
            u2 v = cmul(X, tc, ts);
            CHAIN_ADV(tc, ts, s5c, s5s);

            // 32-pt cross-lane FFT (radix-2 DIF, output bitrev in lane)
            BFLY2(16, T1c, T1s, S16);
            BFLY2(8,  T2c, T2s, S8);
            BFLY2(4,  T3c, T3s, S4);
            BFLY2(2,  T4c, T4s, S2);
            {   // last stage: twiddle = 1
                float vx_, vy_;
                upk2(vx_, vy_, v);
                float ox_ = __shfl_xor_sync(0xffffffffu, vx_, 1);
                float oy_ = __shfl_xor_sync(0xffffffffu, vy_, 1);
                v = fma2(S1, v, pk2(ox_, oy_));
            }

            // phase C: lane holds X[k2 = br]; q = k + 20*br; fp16 smem store
            float vx, vy;
            upk2(vx, vy, v);
            buf[(k + 20 * br) * SQ_PAD + w] = __float22half2_rn(make_float2(vx, vy));
        }

        CHAIN_ADV(wjc, wjs, s1c, s1s);
    }
#undef BFLY2
#undef CHAIN_ADV
    __syncthreads();

    // ---- phase D: coalesced fp16 global copy ----
    // idx = i*128+tid -> q = idx>>2, c = idx&3 (4 cols = 16B chunks).
    size_t out_base; int stride_q;
    if (MODE == 1) {
        // col = (p*16+cc)*320 + n  ->  out[((p*640+q)*16+cc)*320 + n]
        int pc = base_col / NIM, n0 = base_col % NIM;
        int p = pc >> 4, cc = pc & 15;
        out_base = (size_t)p * (640u * 16u * 320u) + (size_t)cc * 320u + (size_t)n0;
        stride_q = 16 * 320;
    } else {
        // col = (p*640+qq)*16 + coil  ->  out[((p*640+kk)*640+qq)*16 + coil]
        int pq = base_col >> 4, c0 = base_col & 15;
        int p = pq / KOS, qq = pq - p * KOS;
        out_base = (size_t)p * (640u * 640u * 16u) + (size_t)qq * 16u + (size_t)c0;
        stride_q = 640 * 16;
    }
#pragma unroll
    for (int i = 0; i < 20; i++) {
        int idx = i * 128 + tid;            // 0..2559
        int q = idx >> 2, c = idx & 3;
        out[out_base + (size_t)q * stride_q + c] = buf[q * SQ_PAD + c];
    }
}

// ---------------------------------------------------------------------------
// KB interpolation (R13-proven version): 6x6 taps; each thread handles TWO
// adjacent coils via one 8B load per tap. Block = 256 = 32 points x 8 pairs.
// ---------------------------------------------------------------------------
__global__ __launch_bounds__(256) void interp_kernel(
    const float* __restrict__ traj, float2* __restrict__ out)
{
    __shared__ float s_wh[32][JTAPS], s_ww[32][JTAPS];
    __shared__ int   s_ih[32][JTAPS], s_iw[32][JTAPS];
    __shared__ float s_pr[32], s_pi[32];

    const int tid = threadIdx.x;
    const int cp  = tid & 7;                      // coil pair 0..7
    const int li  = tid >> 3;                     // point within block 0..31
    const int p   = blockIdx.y;
    const int l   = blockIdx.x * 32 + li;

    const float inv_i0a = g_inv_i0a;

    if (cp < 2) {
        float om = traj[(long)(p * 2 + cp) * KLEN + l];
        float t  = om * (320.0f / PI_F);
        float base = floorf(t - 3.0f);
#pragma unroll
        for (int j = 0; j < JTAPS; j++) {
            float kf  = base + (float)(j + 1);
            float u   = t - kf;
            float ua  = u * (1.0f / 3.0f);
            float arg = fmaxf(1.0f - ua * ua, 0.0f);
            float w   = i0f_dev(ALPHA_F * sqrtf(arg)) * inv_i0a;
            int ki  = (int)kf;
            int idx = ki % KOS; if (idx < 0) idx += KOS;
            if (cp == 0) { s_wh[li][j] = w; s_ih[li][j] = idx; }
            else         { s_ww[li][j] = w; s_iw[li][j] = idx; }
        }
        if (cp == 0) {
            float om1 = traj[(long)(p * 2 + 1) * KLEN + l];
            float th  = 160.0f * (om + om1);
            float sp, cpn;
            sincosf(th, &sp, &cpn);
            s_pr[li] = cpn; s_pi[li] = sp;
        }
    }
    __syncthreads();

    float wh[JTAPS], ww[JTAPS];
    int   ihx[JTAPS], iwx[JTAPS];
#pragma unroll
    for (int j = 0; j < JTAPS; j++) {
        wh[j]  = s_wh[li][j];
        ww[j]  = s_ww[li][j];
        ihx[j] = s_ih[li][j];
        iwx[j] = s_iw[li][j] * 8;     // in uint2 (8B = 2 coils) units
    }
    const float pr = s_pr[li], pi = s_pi[li];

    const uint2* Gp = (const uint2*)(g_Gh + (size_t)p * (640u * 640u * 16u))
                      + cp;
    float ar0 = 0.0f, ai0 = 0.0f, ar1 = 0.0f, ai1 = 0.0f;
#pragma unroll
    for (int j1 = 0; j1 < JTAPS; j1++) {
        const uint2* row = Gp + (size_t)ihx[j1] * (640u * 8u);
        const float w1 = wh[j1];
#pragma unroll
        for (int j2 = 0; j2 < JTAPS; j2++) {
            uint2 pair = row[iwx[j2]];
            float2 v0 = __half22float2(*(const __half2*)&pair.x);
            float2 v1 = __half22float2(*(const __half2*)&pair.y);
            float  w = w1 * ww[j2];
            ar0 = fmaf(v0.x, w, ar0);
            ai0 = fmaf(v0.y, w, ai0);
            ar1 = fmaf(v1.x, w, ar1);
            ai1 = fmaf(v1.y, w, ai1);
        }
    }
    const float sc = 1.0f / 640.0f;               // ortho norm
    float2 o0, o1;
    o0.x = (ar0 * pr - ai0 * pi) * sc;
    o0.y = (ar0 * pi + ai0 * pr) * sc;
    o1.x = (ar1 * pr - ai1 * pi) * sc;
    o1.y = (ar1 * pi + ai1 * pr) * sc;
    out[(long)((p * NCOIL + 2 * cp) * KLEN) + l] = o0;
    out[(long)((p * NCOIL + 2 * cp + 1) * KLEN) + l] = o1;
}

// ---------------------------------------------------------------------------
// Launch
// ---------------------------------------------------------------------------
extern "C" void kernel_launch(void* const* d_in, const int* in_sizes, int n_in,
                              void* d_out, int out_size)
{
    const float2* image = (const float2*)d_in[0];   // (1,5,8,2,320,320,2)
    const float*  traj  = (const float*)d_in[1];    // (5,2,16000)

    __half2 *Rhp, *Ghp;
    cudaGetSymbolAddress((void**)&Rhp, g_Rh);
    cudaGetSymbolAddress((void**)&Ghp, g_Gh);

    // Probe no-op: keeps ncu's -s/-c window landing on fft640_kernel<2>.
    probe_kernel<<<1, 32>>>();

    init_tables_kernel<<<2, 256>>>();

    // Stage 1: FFT along m (width), apodized.  cols = (p,c,n): 25600 -> 6400 blocks
    fft640_kernel<1><<<(PH * NCOIL * NIM) / 4, 128>>>((const void*)image, Rhp);

    // Stage 2: FFT along n (height).  cols = (p,q,c): 51200 -> 12800 blocks
    fft640_kernel<2><<<(PH * KOS * NCOIL) / 4, 128>>>((const void*)Rhp, Ghp);

    // Stage 3: KB interpolation + recentering phase + ortho scale
    {
        dim3 grid(KLEN / 32, PH);
        interp_kernel<<<grid, 256>>>(traj, (float2*)d_out);
    }
}

// round 16
// speedup vs baseline: 1.1045x; 1.1045x over previous
#include <cuda_runtime.h>
#include <cuda_bf16.h>
#include <cuda_fp16.h>
#include <math.h>

// Problem constants
#define PH     5
#define NCOIL  16          // ch*d = 8*2
#define NIM    320         // H = W
#define KOS    640         // 2x oversampled grid
#define KLEN   16000
#define JTAPS  6
#define ALPHA_F 14.04f     // 2.34 * 6
#define PI_F   3.14159265358979323846f

// ---------------------------------------------------------------------------
// Static device scratch (no allocations allowed)
// ---------------------------------------------------------------------------
__device__ __half2 g_Rh[PH * KOS * NCOIL * NIM];     // 65.5 MB
__device__ __half2 g_Gh[PH * KOS * KOS * NCOIL];     // 131 MB
__device__ float   g_sh[NIM];                        // apodization (sh == sw)
__device__ float   g_inv_i0a;                        // 1 / I0(alpha)

// ---------------------------------------------------------------------------
// Packed f32x2 helpers. One u2 holds the SAME component (re or im) of TWO
// columns: v_re = (colA.re, colB.re).
// ---------------------------------------------------------------------------
typedef unsigned long long u2;

__device__ __forceinline__ u2 pk2(float lo, float hi) {
    u2 r; asm("mov.b64 %0, {%1, %2};" : "=l"(r) : "f"(lo), "f"(hi)); return r;
}
__device__ __forceinline__ void upk2(float& lo, float& hi, u2 v) {
    asm("mov.b64 {%0, %1}, %2;" : "=f"(lo), "=f"(hi) : "l"(v));
}
__device__ __forceinline__ u2 dup2(float x) { return pk2(x, x); }
__device__ __forceinline__ u2 fma2(u2 a, u2 b, u2 c) {
    u2 d; asm("fma.rn.f32x2 %0, %1, %2, %3;" : "=l"(d) : "l"(a), "l"(b), "l"(c)); return d;
}
__device__ __forceinline__ u2 mul2(u2 a, u2 b) {
    u2 d; asm("mul.rn.f32x2 %0, %1, %2;" : "=l"(d) : "l"(a), "l"(b)); return d;
}
__device__ __forceinline__ u2 add2(u2 a, u2 b) {
    u2 d; asm("add.rn.f32x2 %0, %1, %2;" : "=l"(d) : "l"(a), "l"(b)); return d;
}
// unpack a re/im-plane half2 (compA, compB) to packed fp32 u2
__device__ __forceinline__ u2 upkh(__half2 h) {
    float2 f = __half22float2(h);
    return pk2(f.x, f.y);
}

// (Xr,Xi) += (zr,zi) * (wr + i wi), wr/wi compile-time: branches fold.
__device__ __forceinline__ void cfma_ri(u2& Xr, u2& Xi, u2 zr, u2 zi,
                                        float wr, float wi) {
    if (wi == 0.0f) {
        if (wr == 1.0f)       { Xr = add2(Xr, zr); Xi = add2(Xi, zi); }
        else                  { Xr = fma2(zr, dup2(wr), Xr); Xi = fma2(zi, dup2(wr), Xi); }
    } else if (wr == 0.0f)    { Xr = fma2(zi, dup2(-wi), Xr); Xi = fma2(zr, dup2(wi), Xi); }
    else {
        Xr = fma2(zr, dup2(wr), Xr); Xr = fma2(zi, dup2(-wi), Xr);
        Xi = fma2(zr, dup2(wi), Xi); Xi = fma2(zi, dup2(wr), Xi);
    }
}

// ---------------------------------------------------------------------------
// Compile-time twiddle tables
// ---------------------------------------------------------------------------
__device__ constexpr float W5R[5] = {
    1.0f, 0.30901699437495f, -0.80901699437495f, -0.80901699437495f, 0.30901699437495f };
__device__ constexpr float W5I[5] = {
    0.0f, -0.95105651629515f, -0.58778525229247f, 0.58778525229247f, 0.95105651629515f };
__device__ constexpr float W20R[20] = {
    1.0f, 0.95105651629515f, 0.80901699437495f, 0.58778525229247f, 0.30901699437495f,
    0.0f, -0.30901699437495f, -0.58778525229247f, -0.80901699437495f, -0.95105651629515f,
    -1.0f, -0.95105651629515f, -0.80901699437495f, -0.58778525229247f, -0.30901699437495f,
    0.0f, 0.30901699437495f, 0.58778525229247f, 0.80901699437495f, 0.95105651629515f };
__device__ constexpr float W20I[20] = {
    0.0f, -0.30901699437495f, -0.58778525229247f, -0.80901699437495f, -0.95105651629515f,
    -1.0f, -0.95105651629515f, -0.80901699437495f, -0.58778525229247f, -0.30901699437495f,
    0.0f, 0.30901699437495f, 0.58778525229247f, 0.80901699437495f, 0.95105651629515f,
    1.0f, 0.95105651629515f, 0.80901699437495f, 0.58778525229247f, 0.30901699437495f };

// ---------------------------------------------------------------------------
// Modified Bessel I0 (Abramowitz & Stegun, rel err ~2e-7)
// ---------------------------------------------------------------------------
__device__ __forceinline__ float i0f_dev(float x) {
    if (x < 3.75f) {
        float t = x * (1.0f / 3.75f);
        t *= t;
        return 1.0f + t * (3.5156229f + t * (3.0899424f + t * (1.2067492f +
               t * (0.2659732f + t * (0.0360768f + t * 0.0045813f)))));
    } else {
        float t = 3.75f / x;
        float p = 0.39894228f + t * (0.01328592f + t * (0.00225319f +
                  t * (-0.00157565f + t * (0.00916281f + t * (-0.02057706f +
                  t * (0.02635537f + t * (-0.01647633f + t * 0.00392377f)))))));
        return p * expf(x) * rsqrtf(x);
    }
}

// Probe: no-op kernel keeps the ncu -s/-c window landing on fft640<2>.
__global__ void probe_kernel() {}

__global__ void init_tables_kernel() {
    int n = blockIdx.x * blockDim.x + threadIdx.x;
    if (n < NIM) {
        float i0a = i0f_dev(ALPHA_F);
        if (n == 0) g_inv_i0a = 1.0f / i0a;
        float nn = (float)(n - NIM / 2);
        float u  = nn * (1.0f / (float)KOS);
        float w  = PI_F * (float)JTAPS * u;
        float z2 = w * w - ALPHA_F * ALPHA_F;
        float z  = fmaxf(sqrtf(fabsf(z2)), 1e-6f);
        float core = (z2 > 0.0f) ? (sinf(z) / z) : (sinhf(z) / z);
        float ft = core * ((float)JTAPS / i0a);
        g_sh[n] = 1.0f / ft;
    }
}

// ---------------------------------------------------------------------------
// Four-step 640-pt DFT, zero-padded length-320 input.
// Block = 128 threads = 4 warps; each warp processes 2 columns (re/im
// plane packing: one u2 = component of both cols, all twiddle math shared
// — R14's best per-instruction form). Register diet vs R14:
//   * x kept as __half2 re/im planes (20 regs, not 40); unpacked per j
//   * no negated twiddle shadows (negate via shared NEG1 at use)
//   * T4 (*-i) via 2 SELs instead of cmul registers
// -> ~95 regs under the (128,5) 102-reg cap: 20 warps/SM AND spare regs
// so ptxas can overlap the 4 independent k-chains per j (R14 profile:
// 128-reg wall, occ 23.7%, issue 46% = stall-bound with no ILP slack).
//   n = 32*n1 + n2 (n1<20; nonzero n1<10),  k = k1 + 20*k2.
// MODE 1: in = fp32 image (apodized, ->half) -> g_Rh. MODE 2: g_Rh -> g_Gh.
// ---------------------------------------------------------------------------
#define SQ_PAD 9                       // buf row stride (8 cols + 1 pad)
#define BUF_H2 (KOS * SQ_PAD)          // 5760 half2 = 23040 B

template <int MODE>
__global__ __launch_bounds__(128, 5) void fft640_kernel(
    const void* __restrict__ inv, __half2* __restrict__ out)
{
    __shared__ __half2 buf[BUF_H2];    // buf[loc*SQ_PAD + col_local]

    const int tid  = threadIdx.x;
    const int w    = tid >> 5;         // warp 0..3
    const int lane = tid & 31;

    const int base_col = blockIdx.x * 8;
    const int cl   = 2 * w;            // col_local of colA
    const int colA = base_col + cl;
    const int colB = colA + 1;

    // ---- load 10 inputs x 2 cols into half2 re/im planes ----
    __half2 xhr[10], xhi[10];
    if (MODE == 1) {
        const float2* ipA = (const float2*)inv + (size_t)colA * NIM + lane;
        const float2* ipB = (const float2*)inv + (size_t)colB * NIM + lane;
        float shrA = g_sh[colA % NIM];
        float shrB = g_sh[colB % NIM];
#pragma unroll
        for (int n1 = 0; n1 < 10; n1++) {
            float2 a = ipA[n1 * 32];
            float2 b = ipB[n1 * 32];
            float sn = g_sh[n1 * 32 + lane];
            xhr[n1] = __floats2half2_rn(a.x * (shrA * sn), b.x * (shrB * sn));
            xhi[n1] = __floats2half2_rn(a.y * (shrA * sn), b.y * (shrB * sn));
        }
    } else {
        const __half2* ipA = (const __half2*)inv + (size_t)colA * NIM + lane;
        const __half2* ipB = (const __half2*)inv + (size_t)colB * NIM + lane;
#pragma unroll
        for (int n1 = 0; n1 < 10; n1++) {
            __half2 a = ipA[n1 * 32];
            __half2 b = ipB[n1 * 32];
            xhr[n1] = __lows2half2(a, b);     // (reA, reB)
            xhi[n1] = __highs2half2(a, b);    // (imA, imB)
        }
    }

    // ---- per-lane butterfly twiddles (shared by both columns) ----
    float sc_s, sc_c;
    sincospif(-(float)(lane & 15) * (1.0f / 16.0f), &sc_s, &sc_c);
    const u2 T1c = dup2((lane & 16) ? sc_c : 1.0f);
    const u2 T1s = dup2((lane & 16) ? sc_s : 0.0f);
    sincospif(-(float)(lane & 7) * (1.0f / 8.0f), &sc_s, &sc_c);
    const u2 T2c = dup2((lane & 8) ? sc_c : 1.0f);
    const u2 T2s = dup2((lane & 8) ? sc_s : 0.0f);
    sincospif(-(float)(lane & 3) * (1.0f / 4.0f), &sc_s, &sc_c);
    const u2 T3c = dup2((lane & 4) ? sc_c : 1.0f);
    const u2 T3s = dup2((lane & 4) ? sc_s : 0.0f);
    const bool t4rot = (lane & 2) && (lane & 1);           // W4^1 = -i
    const u2 S16 = dup2((lane & 16) ? -1.0f : 1.0f);
    const u2 S8  = dup2((lane & 8)  ? -1.0f : 1.0f);
    const u2 S4  = dup2((lane & 4)  ? -1.0f : 1.0f);
    const u2 S2  = dup2((lane & 2)  ? -1.0f : 1.0f);
    const u2 S1  = dup2((lane & 1)  ? -1.0f : 1.0f);
    const u2 NEG1 = dup2(-1.0f);
    const int br = (int)(__brev((unsigned)lane) >> 27);    // bitrev5

    // twiddle chain steps: W640^{n2}, W640^{5 n2}  (cos dup, sin dup)
    sincospif(-(float)lane * (1.0f / 320.0f), &sc_s, &sc_c);
    const u2 s1r = dup2(sc_c), s1i = dup2(sc_s);
    sincospif(-(float)lane * (1.0f / 64.0f), &sc_s, &sc_c);
    const u2 s5r = dup2(sc_c), s5i = dup2(sc_s);
    u2 wjr = dup2(1.0f), wji = dup2(0.0f);

#define BFLY_RI(H, TC, TS, SD)                                          \
    do {                                                                \
        u2 o_re = __shfl_xor_sync(0xffffffffu, v_re, (H));              \
        u2 o_im = __shfl_xor_sync(0xffffffffu, v_im, (H));              \
        u2 t_re = fma2((SD), v_re, o_re);                               \
        u2 t_im = fma2((SD), v_im, o_im);                               \
        u2 t_imn = mul2(t_im, NEG1);                                    \
        v_re = fma2(t_imn, (TS), mul2(t_re, (TC)));                     \
        v_im = fma2(t_im,  (TC), mul2(t_re, (TS)));                     \
    } while (0)

    // ---- main loop: j = k % 5 ----
#pragma unroll
    for (int j = 0; j < 5; j++) {
        const int j2 = (2 * j) % 5;
        // A1: F0..F3 for this j (x unpacked per use; rematerialized cheap)
        u2 f0r = upkh(xhr[0]), f0i = upkh(xhi[0]);
        u2 f1r = upkh(xhr[1]), f1i = upkh(xhi[1]);
        u2 f2r = upkh(xhr[2]), f2i = upkh(xhi[2]);
        u2 f3r = upkh(xhr[3]), f3i = upkh(xhi[3]);
        cfma_ri(f0r, f0i, upkh(xhr[4]), upkh(xhi[4]), W5R[j],  W5I[j]);
        cfma_ri(f0r, f0i, upkh(xhr[8]), upkh(xhi[8]), W5R[j2], W5I[j2]);
        cfma_ri(f1r, f1i, upkh(xhr[5]), upkh(xhi[5]), W5R[j],  W5I[j]);
        cfma_ri(f1r, f1i, upkh(xhr[9]), upkh(xhi[9]), W5R[j2], W5I[j2]);
        cfma_ri(f2r, f2i, upkh(xhr[6]), upkh(xhi[6]), W5R[j],  W5I[j]);
        cfma_ri(f3r, f3i, upkh(xhr[7]), upkh(xhi[7]), W5R[j],  W5I[j]);

        // inner twiddle chain starts at wj
        u2 tr = wjr, ti = wji;

#pragma unroll
        for (int t = 0; t < 4; t++) {
            const int k  = j + 5 * t;
            const int ka = (2 * k) % 20, kb = (3 * k) % 20;
            u2 Xr = f0r, Xi = f0i;
            cfma_ri(Xr, Xi, f1r, f1i, W20R[k],  W20I[k]);
            cfma_ri(Xr, Xi, f2r, f2i, W20R[ka], W20I[ka]);
            cfma_ri(Xr, Xi, f3r, f3i, W20R[kb], W20I[kb]);

            // apply W640^{n2 k}
            u2 v_re = fma2(mul2(Xi, NEG1), ti, mul2(Xr, tr));
            u2 v_im = fma2(Xi, tr,  mul2(Xr, ti));
            // advance inner chain by step5
            {
                u2 nr = fma2(mul2(ti, NEG1), s5i, mul2(tr, s5r));
                u2 ni = fma2(ti, s5r,  mul2(tr, s5i));
                tr = nr; ti = ni;
            }

            // 32-pt cross-lane FFT (radix-2 DIF)
            BFLY_RI(16, T1c, T1s, S16);
            BFLY_RI(8,  T2c, T2s, S8);
            BFLY_RI(4,  T3c, T3s, S4);
            {   // stage H=2: twiddle is 1 or -i -> swap + negate via SEL
                u2 o_re = __shfl_xor_sync(0xffffffffu, v_re, 2);
                u2 o_im = __shfl_xor_sync(0xffffffffu, v_im, 2);
                u2 t_re = fma2(S2, v_re, o_re);
                u2 t_im = fma2(S2, v_im, o_im);
                v_re = t4rot ? t_im : t_re;
                v_im = t4rot ? mul2(t_re, NEG1) : t_im;
            }
            {   // last stage: twiddle = 1
                u2 o_re = __shfl_xor_sync(0xffffffffu, v_re, 1);
                u2 o_im = __shfl_xor_sync(0xffffffffu, v_im, 1);
                v_re = fma2(S1, v_re, o_re);
                v_im = fma2(S1, v_im, o_im);
            }

            // phase C: lane holds X[k2 = br] for both cols; fp16 store
            float rA, rB, iA, iB;
            upk2(rA, rB, v_re);
            upk2(iA, iB, v_im);
            const int loc = (k * 32 + br) * SQ_PAD + cl;
            buf[loc]     = __floats2half2_rn(rA, iA);
            buf[loc + 1] = __floats2half2_rn(rB, iB);
        }

        // advance outer chain by step1
        {
            u2 nr = fma2(mul2(wji, NEG1), s1i, mul2(wjr, s1r));
            u2 ni = fma2(wji, s1r,  mul2(wjr, s1i));
            wjr = nr; wji = ni;
        }
    }
#undef BFLY_RI
    __syncthreads();

    // ---- phase D: remapped coalesced fp16 global copy ----
    // thread -> (k2b = tid>>3 in 0..15, c = tid&7); q = k1 + 20*k2.
    const int k2b = tid >> 3;
    const int c   = tid & 7;
    size_t out_base; int stride_q;
    if (MODE == 1) {
        // col = (p*16+cc)*320 + n  ->  out[((p*640+q)*16+cc)*320 + n]
        int pc = base_col / NIM, n0 = base_col % NIM;
        int p = pc >> 4, cc = pc & 15;
        out_base = (size_t)p * (640u * 16u * 320u) + (size_t)cc * 320u
                 + (size_t)n0 + c;
        stride_q = 16 * 320;
    } else {
        // col = (p*640+qq)*16 + coil  ->  out[((p*640+kk)*640+qq)*16 + coil]
        int pq = base_col >> 4, c0 = base_col & 15;
        int p = pq / KOS, qq = pq - p * KOS;
        out_base = (size_t)p * (640u * 640u * 16u) + (size_t)qq * 16u
                 + (size_t)c0 + c;
        stride_q = 640 * 16;
    }
#pragma unroll
    for (int k1 = 0; k1 < 20; k1++) {
#pragma unroll
        for (int h = 0; h < 2; h++) {
            const int k2 = k2b + 16 * h;
            out[out_base + (size_t)(k1 + 20 * k2) * stride_q] =
                buf[(k1 * 32 + k2) * SQ_PAD + c];
        }
    }
}

// ---------------------------------------------------------------------------
// KB interpolation (R13-proven version): 6x6 taps; each thread handles TWO
// adjacent coils via one 8B load per tap. Block = 256 = 32 points x 8 pairs.
// ---------------------------------------------------------------------------
__global__ __launch_bounds__(256) void interp_kernel(
    const float* __restrict__ traj, float2* __restrict__ out)
{
    __shared__ float s_wh[32][JTAPS], s_ww[32][JTAPS];
    __shared__ int   s_ih[32][JTAPS], s_iw[32][JTAPS];
    __shared__ float s_pr[32], s_pi[32];

    const int tid = threadIdx.x;
    const int cp  = tid & 7;                      // coil pair 0..7
    const int li  = tid >> 3;                     // point within block 0..31
    const int p   = blockIdx.y;
    const int l   = blockIdx.x * 32 + li;

    const float inv_i0a = g_inv_i0a;

    if (cp < 2) {
        float om = traj[(long)(p * 2 + cp) * KLEN + l];
        float t  = om * (320.0f / PI_F);
        float base = floorf(t - 3.0f);
#pragma unroll
        for (int j = 0; j < JTAPS; j++) {
            float kf  = base + (float)(j + 1);
            float u   = t - kf;
            float ua  = u * (1.0f / 3.0f);
            float arg = fmaxf(1.0f - ua * ua, 0.0f);
            float w   = i0f_dev(ALPHA_F * sqrtf(arg)) * inv_i0a;
            int ki  = (int)kf;
            int idx = ki % KOS; if (idx < 0) idx += KOS;
            if (cp == 0) { s_wh[li][j] = w; s_ih[li][j] = idx; }
            else         { s_ww[li][j] = w; s_iw[li][j] = idx; }
        }
        if (cp == 0) {
            float om1 = traj[(long)(p * 2 + 1) * KLEN + l];
            float th  = 160.0f * (om + om1);
            float sp, cpn;
            sincosf(th, &sp, &cpn);
            s_pr[li] = cpn; s_pi[li] = sp;
        }
    }
    __syncthreads();

    float wh[JTAPS], ww[JTAPS];
    int   ihx[JTAPS], iwx[JTAPS];
#pragma unroll
    for (int j = 0; j < JTAPS; j++) {
        wh[j]  = s_wh[li][j];
        ww[j]  = s_ww[li][j];
        ihx[j] = s_ih[li][j];
        iwx[j] = s_iw[li][j] * 8;     // in uint2 (8B = 2 coils) units
    }
    const float pr = s_pr[li], pi = s_pi[li];

    const uint2* Gp = (const uint2*)(g_Gh + (size_t)p * (640u * 640u * 16u))
                      + cp;
    float ar0 = 0.0f, ai0 = 0.0f, ar1 = 0.0f, ai1 = 0.0f;
#pragma unroll
    for (int j1 = 0; j1 < JTAPS; j1++) {
        const uint2* row = Gp + (size_t)ihx[j1] * (640u * 8u);
        const float w1 = wh[j1];
#pragma unroll
        for (int j2 = 0; j2 < JTAPS; j2++) {
            uint2 pair = row[iwx[j2]];
            float2 v0 = __half22float2(*(const __half2*)&pair.x);
            float2 v1 = __half22float2(*(const __half2*)&pair.y);
            float  w = w1 * ww[j2];
            ar0 = fmaf(v0.x, w, ar0);
            ai0 = fmaf(v0.y, w, ai0);
            ar1 = fmaf(v1.x, w, ar1);
            ai1 = fmaf(v1.y, w, ai1);
        }
    }
    const float sc = 1.0f / 640.0f;               // ortho norm
    float2 o0, o1;
    o0.x = (ar0 * pr - ai0 * pi) * sc;
    o0.y = (ar0 * pi + ai0 * pr) * sc;
    o1.x = (ar1 * pr - ai1 * pi) * sc;
    o1.y = (ar1 * pi + ai1 * pr) * sc;
    out[(long)((p * NCOIL + 2 * cp) * KLEN) + l] = o0;
    out[(long)((p * NCOIL + 2 * cp + 1) * KLEN) + l] = o1;
}

// ---------------------------------------------------------------------------
// Launch
// ---------------------------------------------------------------------------
extern "C" void kernel_launch(void* const* d_in, const int* in_sizes, int n_in,
                              void* d_out, int out_size)
{
    const float2* image = (const float2*)d_in[0];   // (1,5,8,2,320,320,2)
    const float*  traj  = (const float*)d_in[1];    // (5,2,16000)

    __half2 *Rhp, *Ghp;
    cudaGetSymbolAddress((void**)&Rhp, g_Rh);
    cudaGetSymbolAddress((void**)&Ghp, g_Gh);

    // Probe no-op: keeps ncu's -s/-c window landing on fft640_kernel<2>.
    probe_kernel<<<1, 32>>>();

    init_tables_kernel<<<2, 256>>>();

    // Stage 1: FFT along m (width), apodized.  cols = (p,c,n): 25600 -> 3200 blocks
    fft640_kernel<1><<<(PH * NCOIL * NIM) / 8, 128>>>((const void*)image, Rhp);

    // Stage 2: FFT along n (height).  cols = (p,q,c): 51200 -> 6400 blocks
    fft640_kernel<2><<<(PH * KOS * NCOIL) / 8, 128>>>((const void*)Rhp, Ghp);

    // Stage 3: KB interpolation + recentering phase + ortho scale
    {
        dim3 grid(KLEN / 32, PH);
        interp_kernel<<<grid, 256>>>(traj, (float2*)d_out);
    }
}

// round 17
// speedup vs baseline: 1.1157x; 1.0101x over previous
#include <cuda_runtime.h>
#include <cuda_bf16.h>
#include <cuda_fp16.h>
#include <math.h>

// Problem constants
#define PH     5
#define NCOIL  16          // ch*d = 8*2
#define NIM    320         // H = W
#define KOS    640         // 2x oversampled grid
#define KLEN   16000
#define JTAPS  6
#define ALPHA_F 14.04f     // 2.34 * 6
#define PI_F   3.14159265358979323846f

// ---------------------------------------------------------------------------
// Static device scratch (no allocations allowed)
// ---------------------------------------------------------------------------
__device__ __half2 g_Rh[PH * KOS * NCOIL * NIM];     // 65.5 MB
__device__ __half2 g_Gh[PH * KOS * KOS * NCOIL];     // 131 MB
__device__ float   g_sh[NIM];                        // apodization (sh == sw)
__device__ float   g_inv_i0a;                        // 1 / I0(alpha)

// ---------------------------------------------------------------------------
// Packed f32x2 helpers. One u2 holds the SAME component (re or im) of TWO
// columns: v_re = (colA.re, colB.re).
// ---------------------------------------------------------------------------
typedef unsigned long long u2;

__device__ __forceinline__ u2 pk2(float lo, float hi) {
    u2 r; asm("mov.b64 %0, {%1, %2};" : "=l"(r) : "f"(lo), "f"(hi)); return r;
}
__device__ __forceinline__ void upk2(float& lo, float& hi, u2 v) {
    asm("mov.b64 {%0, %1}, %2;" : "=f"(lo), "=f"(hi) : "l"(v));
}
__device__ __forceinline__ u2 dup2(float x) { return pk2(x, x); }
__device__ __forceinline__ u2 fma2(u2 a, u2 b, u2 c) {
    u2 d; asm("fma.rn.f32x2 %0, %1, %2, %3;" : "=l"(d) : "l"(a), "l"(b), "l"(c)); return d;
}
__device__ __forceinline__ u2 mul2(u2 a, u2 b) {
    u2 d; asm("mul.rn.f32x2 %0, %1, %2;" : "=l"(d) : "l"(a), "l"(b)); return d;
}
__device__ __forceinline__ u2 add2(u2 a, u2 b) {
    u2 d; asm("add.rn.f32x2 %0, %1, %2;" : "=l"(d) : "l"(a), "l"(b)); return d;
}
// unpack a re/im-plane half2 (compA, compB) to packed fp32 u2
__device__ __forceinline__ u2 upkh(__half2 h) {
    float2 f = __half22float2(h);
    return pk2(f.x, f.y);
}

// (Xr,Xi) += (zr,zi) * (wr + i wi), wr/wi compile-time: branches fold.
__device__ __forceinline__ void cfma_ri(u2& Xr, u2& Xi, u2 zr, u2 zi,
                                        float wr, float wi) {
    if (wi == 0.0f) {
        if (wr == 1.0f)       { Xr = add2(Xr, zr); Xi = add2(Xi, zi); }
        else                  { Xr = fma2(zr, dup2(wr), Xr); Xi = fma2(zi, dup2(wr), Xi); }
    } else if (wr == 0.0f)    { Xr = fma2(zi, dup2(-wi), Xr); Xi = fma2(zr, dup2(wi), Xi); }
    else {
        Xr = fma2(zr, dup2(wr), Xr); Xr = fma2(zi, dup2(-wi), Xr);
        Xi = fma2(zr, dup2(wi), Xi); Xi = fma2(zi, dup2(wr), Xi);
    }
}

// ---------------------------------------------------------------------------
// Compile-time twiddle tables
// ---------------------------------------------------------------------------
__device__ constexpr float W5R[5] = {
    1.0f, 0.30901699437495f, -0.80901699437495f, -0.80901699437495f, 0.30901699437495f };
__device__ constexpr float W5I[5] = {
    0.0f, -0.95105651629515f, -0.58778525229247f, 0.58778525229247f, 0.95105651629515f };
__device__ constexpr float W20R[20] = {
    1.0f, 0.95105651629515f, 0.80901699437495f, 0.58778525229247f, 0.30901699437495f,
    0.0f, -0.30901699437495f, -0.58778525229247f, -0.80901699437495f, -0.95105651629515f,
    -1.0f, -0.95105651629515f, -0.80901699437495f, -0.58778525229247f, -0.30901699437495f,
    0.0f, 0.30901699437495f, 0.58778525229247f, 0.80901699437495f, 0.95105651629515f };
__device__ constexpr float W20I[20] = {
    0.0f, -0.30901699437495f, -0.58778525229247f, -0.80901699437495f, -0.95105651629515f,
    -1.0f, -0.95105651629515f, -0.80901699437495f, -0.58778525229247f, -0.30901699437495f,
    0.0f, 0.30901699437495f, 0.58778525229247f, 0.80901699437495f, 0.95105651629515f,
    1.0f, 0.95105651629515f, 0.80901699437495f, 0.58778525229247f, 0.30901699437495f };

// ---------------------------------------------------------------------------
// Modified Bessel I0 (Abramowitz & Stegun, rel err ~2e-7)
// ---------------------------------------------------------------------------
__device__ __forceinline__ float i0f_dev(float x) {
    if (x < 3.75f) {
        float t = x * (1.0f / 3.75f);
        t *= t;
        return 1.0f + t * (3.5156229f + t * (3.0899424f + t * (1.2067492f +
               t * (0.2659732f + t * (0.0360768f + t * 0.0045813f)))));
    } else {
        float t = 3.75f / x;
        float p = 0.39894228f + t * (0.01328592f + t * (0.00225319f +
                  t * (-0.00157565f + t * (0.00916281f + t * (-0.02057706f +
                  t * (0.02635537f + t * (-0.01647633f + t * 0.00392377f)))))));
        return p * expf(x) * rsqrtf(x);
    }
}

// Probe: no-op kernel keeps the ncu -s/-c window landing on fft640<2>.
__global__ void probe_kernel() {}

__global__ void init_tables_kernel() {
    int n = blockIdx.x * blockDim.x + threadIdx.x;
    if (n < NIM) {
        float i0a = i0f_dev(ALPHA_F);
        if (n == 0) g_inv_i0a = 1.0f / i0a;
        float nn = (float)(n - NIM / 2);
        float u  = nn * (1.0f / (float)KOS);
        float w  = PI_F * (float)JTAPS * u;
        float z2 = w * w - ALPHA_F * ALPHA_F;
        float z  = fmaxf(sqrtf(fabsf(z2)), 1e-6f);
        float core = (z2 > 0.0f) ? (sinf(z) / z) : (sinhf(z) / z);
        float ft = core * ((float)JTAPS / i0a);
        g_sh[n] = 1.0f / ft;
    }
}

// ---------------------------------------------------------------------------
// Four-step 640-pt DFT, zero-padded length-320 input.
// Block = 128 threads = 4 warps; each warp processes 2 columns (re/im
// plane packing). NEW vs R16: the inner k-loop is 2-WAY SOFTWARE
// PIPELINED — t-iterations are processed in pairs (k, k+5) with the five
// butterfly stages interleaved, so each shfl's 26-cycle latency window is
// filled by the sibling chain's work. (R14-R16 profiles proved ptxas
// never overlaps the chains on its own: issue stuck at 46-52%.)
//   n = 32*n1 + n2 (n1<20; nonzero n1<10),  k = k1 + 20*k2.
// MODE 1: in = fp32 image (apodized, ->half) -> g_Rh. MODE 2: g_Rh -> g_Gh.
// ---------------------------------------------------------------------------
#define SQ_PAD 9                       // buf row stride (8 cols + 1 pad)
#define BUF_H2 (KOS * SQ_PAD)          // 5760 half2 = 23040 B

template <int MODE>
__global__ __launch_bounds__(128, 4) void fft640_kernel(
    const void* __restrict__ inv, __half2* __restrict__ out)
{
    __shared__ __half2 buf[BUF_H2];    // buf[loc*SQ_PAD + col_local]

    const int tid  = threadIdx.x;
    const int w    = tid >> 5;         // warp 0..3
    const int lane = tid & 31;

    const int base_col = blockIdx.x * 8;
    const int cl   = 2 * w;            // col_local of colA
    const int colA = base_col + cl;
    const int colB = colA + 1;

    // ---- load 10 inputs x 2 cols into half2 re/im planes ----
    __half2 xhr[10], xhi[10];
    if (MODE == 1) {
        const float2* ipA = (const float2*)inv + (size_t)colA * NIM + lane;
        const float2* ipB = (const float2*)inv + (size_t)colB * NIM + lane;
        float shrA = g_sh[colA % NIM];
        float shrB = g_sh[colB % NIM];
#pragma unroll
        for (int n1 = 0; n1 < 10; n1++) {
            float2 a = ipA[n1 * 32];
            float2 b = ipB[n1 * 32];
            float sn = g_sh[n1 * 32 + lane];
            xhr[n1] = __floats2half2_rn(a.x * (shrA * sn), b.x * (shrB * sn));
            xhi[n1] = __floats2half2_rn(a.y * (shrA * sn), b.y * (shrB * sn));
        }
    } else {
        const __half2* ipA = (const __half2*)inv + (size_t)colA * NIM + lane;
        const __half2* ipB = (const __half2*)inv + (size_t)colB * NIM + lane;
#pragma unroll
        for (int n1 = 0; n1 < 10; n1++) {
            __half2 a = ipA[n1 * 32];
            __half2 b = ipB[n1 * 32];
            xhr[n1] = __lows2half2(a, b);     // (reA, reB)
            xhi[n1] = __highs2half2(a, b);    // (imA, imB)
        }
    }

    // ---- per-lane butterfly twiddles (shared by both columns) ----
    float sc_s, sc_c;
    sincospif(-(float)(lane & 15) * (1.0f / 16.0f), &sc_s, &sc_c);
    const u2 T1c = dup2((lane & 16) ? sc_c : 1.0f);
    const u2 T1s = dup2((lane & 16) ? sc_s : 0.0f);
    sincospif(-(float)(lane & 7) * (1.0f / 8.0f), &sc_s, &sc_c);
    const u2 T2c = dup2((lane & 8) ? sc_c : 1.0f);
    const u2 T2s = dup2((lane & 8) ? sc_s : 0.0f);
    sincospif(-(float)(lane & 3) * (1.0f / 4.0f), &sc_s, &sc_c);
    const u2 T3c = dup2((lane & 4) ? sc_c : 1.0f);
    const u2 T3s = dup2((lane & 4) ? sc_s : 0.0f);
    const bool t4rot = (lane & 2) && (lane & 1);           // W4^1 = -i
    const u2 S16 = dup2((lane & 16) ? -1.0f : 1.0f);
    const u2 S8  = dup2((lane & 8)  ? -1.0f : 1.0f);
    const u2 S4  = dup2((lane & 4)  ? -1.0f : 1.0f);
    const u2 S2  = dup2((lane & 2)  ? -1.0f : 1.0f);
    const u2 S1  = dup2((lane & 1)  ? -1.0f : 1.0f);
    const u2 NEG1 = dup2(-1.0f);
    const int br = (int)(__brev((unsigned)lane) >> 27);    // bitrev5

    // twiddle chain steps: W640^{n2}, W640^{5 n2}  (cos dup, sin dup)
    sincospif(-(float)lane * (1.0f / 320.0f), &sc_s, &sc_c);
    const u2 s1r = dup2(sc_c), s1i = dup2(sc_s);
    sincospif(-(float)lane * (1.0f / 64.0f), &sc_s, &sc_c);
    const u2 s5r = dup2(sc_c), s5i = dup2(sc_s);
    u2 wjr = dup2(1.0f), wji = dup2(0.0f);

// Interleaved butterfly stage on BOTH in-flight chains (A and B).
#define BFLY_AB(H, TC, TS, SD)                                          \
    do {                                                                \
        u2 oAr = __shfl_xor_sync(0xffffffffu, vAre, (H));               \
        u2 oAi = __shfl_xor_sync(0xffffffffu, vAim, (H));               \
        u2 oBr = __shfl_xor_sync(0xffffffffu, vBre, (H));               \
        u2 oBi = __shfl_xor_sync(0xffffffffu, vBim, (H));               \
        u2 tAr = fma2((SD), vAre, oAr);                                 \
        u2 tAi = fma2((SD), vAim, oAi);                                 \
        u2 tBr = fma2((SD), vBre, oBr);                                 \
        u2 tBi = fma2((SD), vBim, oBi);                                 \
        vAre = fma2(mul2(tAi, NEG1), (TS), mul2(tAr, (TC)));            \
        vAim = fma2(tAi, (TC), mul2(tAr, (TS)));                        \
        vBre = fma2(mul2(tBi, NEG1), (TS), mul2(tBr, (TC)));            \
        vBim = fma2(tBi, (TC), mul2(tBr, (TS)));                        \
    } while (0)

    // ---- main loop: j = k % 5 ----
#pragma unroll
    for (int j = 0; j < 5; j++) {
        const int j2 = (2 * j) % 5;
        // A1: F0..F3 for this j
        u2 f0r = upkh(xhr[0]), f0i = upkh(xhi[0]);
        u2 f1r = upkh(xhr[1]), f1i = upkh(xhi[1]);
        u2 f2r = upkh(xhr[2]), f2i = upkh(xhi[2]);
        u2 f3r = upkh(xhr[3]), f3i = upkh(xhi[3]);
        cfma_ri(f0r, f0i, upkh(xhr[4]), upkh(xhi[4]), W5R[j],  W5I[j]);
        cfma_ri(f0r, f0i, upkh(xhr[8]), upkh(xhi[8]), W5R[j2], W5I[j2]);
        cfma_ri(f1r, f1i, upkh(xhr[5]), upkh(xhi[5]), W5R[j],  W5I[j]);
        cfma_ri(f1r, f1i, upkh(xhr[9]), upkh(xhi[9]), W5R[j2], W5I[j2]);
        cfma_ri(f2r, f2i, upkh(xhr[6]), upkh(xhi[6]), W5R[j],  W5I[j]);
        cfma_ri(f3r, f3i, upkh(xhr[7]), upkh(xhi[7]), W5R[j],  W5I[j]);

        u2 tr = wjr, ti = wji;

#pragma unroll
        for (int tp = 0; tp < 2; tp++) {
            const int kA = j + 10 * tp;
            const int kB = kA + 5;
            const int kA2 = (2 * kA) % 20, kA3 = (3 * kA) % 20;
            const int kB2 = (2 * kB) % 20, kB3 = (3 * kB) % 20;

            // chain A: recombine + W640 twiddle
            u2 XAr = f0r, XAi = f0i;
            cfma_ri(XAr, XAi, f1r, f1i, W20R[kA],  W20I[kA]);
            cfma_ri(XAr, XAi, f2r, f2i, W20R[kA2], W20I[kA2]);
            cfma_ri(XAr, XAi, f3r, f3i, W20R[kA3], W20I[kA3]);
            u2 vAre = fma2(mul2(XAi, NEG1), ti, mul2(XAr, tr));
            u2 vAim = fma2(XAi, tr, mul2(XAr, ti));
            {   // advance chain by step5
                u2 nr = fma2(mul2(ti, NEG1), s5i, mul2(tr, s5r));
                u2 ni = fma2(ti, s5r, mul2(tr, s5i));
                tr = nr; ti = ni;
            }

            // chain B: recombine + W640 twiddle
            u2 XBr = f0r, XBi = f0i;
            cfma_ri(XBr, XBi, f1r, f1i, W20R[kB],  W20I[kB]);
            cfma_ri(XBr, XBi, f2r, f2i, W20R[kB2], W20I[kB2]);
            cfma_ri(XBr, XBi, f3r, f3i, W20R[kB3], W20I[kB3]);
            u2 vBre = fma2(mul2(XBi, NEG1), ti, mul2(XBr, tr));
            u2 vBim = fma2(XBi, tr, mul2(XBr, ti));
            {   // advance chain by step5
                u2 nr = fma2(mul2(ti, NEG1), s5i, mul2(tr, s5r));
                u2 ni = fma2(ti, s5r, mul2(tr, s5i));
                tr = nr; ti = ni;
            }

            // interleaved 32-pt cross-lane FFT (radix-2 DIF), both chains
            BFLY_AB(16, T1c, T1s, S16);
            BFLY_AB(8,  T2c, T2s, S8);
            BFLY_AB(4,  T3c, T3s, S4);
            {   // stage H=2: twiddle is 1 or -i -> swap + negate via SEL
                u2 oAr = __shfl_xor_sync(0xffffffffu, vAre, 2);
                u2 oAi = __shfl_xor_sync(0xffffffffu, vAim, 2);
                u2 oBr = __shfl_xor_sync(0xffffffffu, vBre, 2);
                u2 oBi = __shfl_xor_sync(0xffffffffu, vBim, 2);
                u2 tAr = fma2(S2, vAre, oAr);
                u2 tAi = fma2(S2, vAim, oAi);
                u2 tBr = fma2(S2, vBre, oBr);
                u2 tBi = fma2(S2, vBim, oBi);
                vAre = t4rot ? tAi : tAr;
                vAim = t4rot ? mul2(tAr, NEG1) : tAi;
                vBre = t4rot ? tBi : tBr;
                vBim = t4rot ? mul2(tBr, NEG1) : tBi;
            }
            {   // last stage: twiddle = 1
                u2 oAr = __shfl_xor_sync(0xffffffffu, vAre, 1);
                u2 oAi = __shfl_xor_sync(0xffffffffu, vAim, 1);
                u2 oBr = __shfl_xor_sync(0xffffffffu, vBre, 1);
                u2 oBi = __shfl_xor_sync(0xffffffffu, vBim, 1);
                vAre = fma2(S1, vAre, oAr);
                vAim = fma2(S1, vAim, oAi);
                vBre = fma2(S1, vBre, oBr);
                vBim = fma2(S1, vBim, oBi);
            }

            // phase C: lane holds X[k2 = br] for both cols; fp16 store
            {
                float rA, rB, iA, iB;
                upk2(rA, rB, vAre);
                upk2(iA, iB, vAim);
                const int locA = (kA * 32 + br) * SQ_PAD + cl;
                buf[locA]     = __floats2half2_rn(rA, iA);
                buf[locA + 1] = __floats2half2_rn(rB, iB);
                upk2(rA, rB, vBre);
                upk2(iA, iB, vBim);
                const int locB = (kB * 32 + br) * SQ_PAD + cl;
                buf[locB]     = __floats2half2_rn(rA, iA);
                buf[locB + 1] = __floats2half2_rn(rB, iB);
            }
        }

        // advance outer chain by step1
        {
            u2 nr = fma2(mul2(wji, NEG1), s1i, mul2(wjr, s1r));
            u2 ni = fma2(wji, s1r, mul2(wjr, s1i));
            wjr = nr; wji = ni;
        }
    }
#undef BFLY_AB
    __syncthreads();

    // ---- phase D: remapped coalesced fp16 global copy ----
    // thread -> (k2b = tid>>3 in 0..15, c = tid&7); q = k1 + 20*k2.
    const int k2b = tid >> 3;
    const int c   = tid & 7;
    size_t out_base; int stride_q;
    if (MODE == 1) {
        // col = (p*16+cc)*320 + n  ->  out[((p*640+q)*16+cc)*320 + n]
        int pc = base_col / NIM, n0 = base_col % NIM;
        int p = pc >> 4, cc = pc & 15;
        out_base = (size_t)p * (640u * 16u * 320u) + (size_t)cc * 320u
                 + (size_t)n0 + c;
        stride_q = 16 * 320;
    } else {
        // col = (p*640+qq)*16 + coil  ->  out[((p*640+kk)*640+qq)*16 + coil]
        int pq = base_col >> 4, c0 = base_col & 15;
        int p = pq / KOS, qq = pq - p * KOS;
        out_base = (size_t)p * (640u * 640u * 16u) + (size_t)qq * 16u
                 + (size_t)c0 + c;
        stride_q = 640 * 16;
    }
#pragma unroll
    for (int k1 = 0; k1 < 20; k1++) {
#pragma unroll
        for (int h = 0; h < 2; h++) {
            const int k2 = k2b + 16 * h;
            out[out_base + (size_t)(k1 + 20 * k2) * stride_q] =
                buf[(k1 * 32 + k2) * SQ_PAD + c];
        }
    }
}

// ---------------------------------------------------------------------------
// KB interpolation (R13-proven version): 6x6 taps; each thread handles TWO
// adjacent coils via one 8B load per tap. Block = 256 = 32 points x 8 pairs.
// ---------------------------------------------------------------------------
__global__ __launch_bounds__(256) void interp_kernel(
    const float* __restrict__ traj, float2* __restrict__ out)
{
    __shared__ float s_wh[32][JTAPS], s_ww[32][JTAPS];
    __shared__ int   s_ih[32][JTAPS], s_iw[32][JTAPS];
    __shared__ float s_pr[32], s_pi[32];

    const int tid = threadIdx.x;
    const int cp  = tid & 7;                      // coil pair 0..7
    const int li  = tid >> 3;                     // point within block 0..31
    const int p   = blockIdx.y;
    const int l   = blockIdx.x * 32 + li;

    const float inv_i0a = g_inv_i0a;

    if (cp < 2) {
        float om = traj[(long)(p * 2 + cp) * KLEN + l];
        float t  = om * (320.0f / PI_F);
        float base = floorf(t - 3.0f);
#pragma unroll
        for (int j = 0; j < JTAPS; j++) {
            float kf  = base + (float)(j + 1);
            float u   = t - kf;
            float ua  = u * (1.0f / 3.0f);
            float arg = fmaxf(1.0f - ua * ua, 0.0f);
            float w   = i0f_dev(ALPHA_F * sqrtf(arg)) * inv_i0a;
            int ki  = (int)kf;
            int idx = ki % KOS; if (idx < 0) idx += KOS;
            if (cp == 0) { s_wh[li][j] = w; s_ih[li][j] = idx; }
            else         { s_ww[li][j] = w; s_iw[li][j] = idx; }
        }
        if (cp == 0) {
            float om1 = traj[(long)(p * 2 + 1) * KLEN + l];
            float th  = 160.0f * (om + om1);
            float sp, cpn;
            sincosf(th, &sp, &cpn);
            s_pr[li] = cpn; s_pi[li] = sp;
        }
    }
    __syncthreads();

    float wh[JTAPS], ww[JTAPS];
    int   ihx[JTAPS], iwx[JTAPS];
#pragma unroll
    for (int j = 0; j < JTAPS; j++) {
        wh[j]  = s_wh[li][j];
        ww[j]  = s_ww[li][j];
        ihx[j] = s_ih[li][j];
        iwx[j] = s_iw[li][j] * 8;     // in uint2 (8B = 2 coils) units
    }
    const float pr = s_pr[li], pi = s_pi[li];

    const uint2* Gp = (const uint2*)(g_Gh + (size_t)p * (640u * 640u * 16u))
                      + cp;
    float ar0 = 0.0f, ai0 = 0.0f, ar1 = 0.0f, ai1 = 0.0f;
#pragma unroll
    for (int j1 = 0; j1 < JTAPS; j1++) {
        const uint2* row = Gp + (size_t)ihx[j1] * (640u * 8u);
        const float w1 = wh[j1];
#pragma unroll
        for (int j2 = 0; j2 < JTAPS; j2++) {
            uint2 pair = row[iwx[j2]];
            float2 v0 = __half22float2(*(const __half2*)&pair.x);
            float2 v1 = __half22float2(*(const __half2*)&pair.y);
            float  w = w1 * ww[j2];
            ar0 = fmaf(v0.x, w, ar0);
            ai0 = fmaf(v0.y, w, ai0);
            ar1 = fmaf(v1.x, w, ar1);
            ai1 = fmaf(v1.y, w, ai1);
        }
    }
    const float sc = 1.0f / 640.0f;               // ortho norm
    float2 o0, o1;
    o0.x = (ar0 * pr - ai0 * pi) * sc;
    o0.y = (ar0 * pi + ai0 * pr) * sc;
    o1.x = (ar1 * pr - ai1 * pi) * sc;
    o1.y = (ar1 * pi + ai1 * pr) * sc;
    out[(long)((p * NCOIL + 2 * cp) * KLEN) + l] = o0;
    out[(long)((p * NCOIL + 2 * cp + 1) * KLEN) + l] = o1;
}

// ---------------------------------------------------------------------------
// Launch
// ---------------------------------------------------------------------------
extern "C" void kernel_launch(void* const* d_in, const int* in_sizes, int n_in,
                              void* d_out, int out_size)
{
    const float2* image = (const float2*)d_in[0];   // (1,5,8,2,320,320,2)
    const float*  traj  = (const float*)d_in[1];    // (5,2,16000)

    __half2 *Rhp, *Ghp;
    cudaGetSymbolAddress((void**)&Rhp, g_Rh);
    cudaGetSymbolAddress((void**)&Ghp, g_Gh);

    // Probe no-op: keeps ncu's -s/-c window landing on fft640_kernel<2>.
    probe_kernel<<<1, 32>>>();

    init_tables_kernel<<<2, 256>>>();

    // Stage 1: FFT along m (width), apodized.  cols = (p,c,n): 25600 -> 3200 blocks
    fft640_kernel<1><<<(PH * NCOIL * NIM) / 8, 128>>>((const void*)image, Rhp);

    // Stage 2: FFT along n (height).  cols = (p,q,c): 51200 -> 6400 blocks
    fft640_kernel<2><<<(PH * KOS * NCOIL) / 8, 128>>>((const void*)Rhp, Ghp);

    // Stage 3: KB interpolation + recentering phase + ortho scale
    {
        dim3 grid(KLEN / 32, PH);
        interp_kernel<<<grid, 256>>>(traj, (float2*)d_out);
    }
}